// round 15
// baseline (speedup 1.0000x reference)
#include <cuda_runtime.h>
#include <cuda_fp16.h>
#include <cstdint>

// Problem dims (fixed by the dataset)
#define BATCH 32
#define F_IN  512
#define T_LEN 256
#define HID   1024
#define OUTD  128

#define NGROUP 4
#define GB     (BATCH / NGROUP)                 // 8 batches per group

// Output layout (floats): spikes0, spikes1, readouts0, readouts1, voltages0, voltages1, counts[2]
#define SOFF0 ((size_t)0)
#define SOFF1 ((size_t)8388608)
#define ROFF0 ((size_t)16777216)
#define ROFF1 ((size_t)17825792)
#define VOFF0 ((size_t)18874368)
#define VOFF1 ((size_t)27262976)
#define CNTOFF ((size_t)35651584)

// ---------------- device scratch ----------------
__device__ float  g_s [(size_t)BATCH * 3 * HID  * T_LEN];    // hidden plane sums (100.7MB)
__device__ float  g_sr[(size_t)BATCH * 3 * OUTD * T_LEN];    // readout plane sums (12.6MB)
__device__ __half g_bTx[(size_t)BATCH * T_LEN * F_IN];       // input spikes^T f16 (8MB)
__device__ __half g_bT [(size_t)BATCH * T_LEN * HID];        // layer spikes^T f16 (16MB)
__device__ __half g_w1h [3 * HID * F_IN];                    // W1 digit planes
__device__ __half g_w2r1[3 * HID * HID + 3 * OUTD * HID];    // W2 planes ++ R1 planes (stacked)
__device__ __half g_r2h [3 * OUTD * HID];                    // R2 digit planes
__device__ unsigned long long g_cnt[2];

// ---------------- baseline-PTX helpers (valid on compute_103) ----------------
__device__ __forceinline__ uint32_t smem_u32(const void* p) {
    uint32_t a;
    asm("{ .reg .u64 t; cvta.to.shared.u64 t, %1; cvt.u32.u64 %0, t; }" : "=r"(a) : "l"(p));
    return a;
}

__device__ __forceinline__ void cp_async16(uint32_t dst, const void* src) {
    asm volatile("cp.async.ca.shared.global [%0], [%1], 16;" :: "r"(dst), "l"(src));
}
#define CP_COMMIT() asm volatile("cp.async.commit_group;" ::: "memory")
#define CP_WAIT0()  asm volatile("cp.async.wait_group 0;" ::: "memory")

__device__ __forceinline__ void ldsm_x4(uint32_t r[4], uint32_t addr) {
    asm volatile("ldmatrix.sync.aligned.m8n8.x4.shared.b16 {%0,%1,%2,%3}, [%4];"
        : "=r"(r[0]), "=r"(r[1]), "=r"(r[2]), "=r"(r[3]) : "r"(addr));
}

// f16 MMA with f32 accumulate. Exact for small-integer operands (all sums < 2^24).
__device__ __forceinline__ void mma_f16(float* d, const uint32_t* a, uint32_t b0, uint32_t b1) {
    asm volatile(
        "mma.sync.aligned.m16n8k16.row.col.f32.f16.f16.f32 "
        "{%0,%1,%2,%3}, {%4,%5,%6,%7}, {%8,%9}, {%0,%1,%2,%3};"
        : "+f"(d[0]), "+f"(d[1]), "+f"(d[2]), "+f"(d[3])
        : "r"(a[0]), "r"(a[1]), "r"(a[2]), "r"(a[3]), "r"(b0), "r"(b1));
}

// ---------------- combined prep kernel ----------------
// Exact 3-digit balanced base-2048 fixed-point split at scale 2^33 for ALL four
// weight matrices in one launch; also zeroes the spike counters.
__device__ __forceinline__ void wsplit(const float* __restrict__ W, __half* __restrict__ out,
                                       int i, int n) {
    double wd = (double)W[i] * 8589934592.0;   // 2^33, exact
    long long q = llrint(wd);
    long long c0 = (q + (1LL << 21)) >> 22;
    long long r  = q - (c0 << 22);
    long long c1 = (r + (1LL << 10)) >> 11;
    long long c2 = r - (c1 << 11);
    out[i]         = __int2half_rn((int)c0);
    out[n + i]     = __int2half_rn((int)c1);
    out[2 * n + i] = __int2half_rn((int)c2);
}

__global__ void prep_all_kernel(const float* __restrict__ W1, const float* __restrict__ W2,
                                const float* __restrict__ R1, const float* __restrict__ R2,
                                __half* __restrict__ w1h, __half* __restrict__ w2r1,
                                __half* __restrict__ r2h) {
    const int n1 = HID * F_IN;            // 524288
    const int n2 = HID * HID;             // 1048576
    const int n3 = OUTD * HID;            // 131072
    const int NTOT = n1 + n2 + 2 * n3;    // 1835008
    int gid = blockIdx.x * blockDim.x + threadIdx.x;
    if (gid == 0) { g_cnt[0] = 0ull; g_cnt[1] = 0ull; }
    for (int i = gid; i < NTOT; i += gridDim.x * blockDim.x) {
        if (i < n1)                wsplit(W1, w1h, i, n1);
        else if (i < n1 + n2)      wsplit(W2, w2r1, i - n1, n2);
        else if (i < n1 + n2 + n3) wsplit(R1, w2r1 + 3 * n2, i - n1 - n2, n3);
        else                       wsplit(R2, r2h, i - n1 - n2 - n3, n3);
    }
}

// in: fp32 [gb, F, T] (values exactly 0/1) -> out: f16 [gb, T, F]  (group-relative b)
__global__ void transpose_h_kernel(const float* __restrict__ in,
                                   __half* __restrict__ outT, int F) {
    __shared__ float tile[32][33];
    const int b = blockIdx.z;
    const int t0 = blockIdx.x * 32, f0 = blockIdx.y * 32;
    const float* inp = in + ((size_t)b * F + f0) * T_LEN + t0;
#pragma unroll
    for (int i = 0; i < 4; i++)
        tile[threadIdx.y + i * 8][threadIdx.x] = inp[(size_t)(threadIdx.y + i * 8) * T_LEN + threadIdx.x];
    __syncthreads();
    __half* op = outT + ((size_t)b * T_LEN + t0) * F + f0;
    const __half one = __float2half(1.0f), zero = __float2half(0.0f);
#pragma unroll
    for (int i = 0; i < 4; i++)
        op[(size_t)(threadIdx.y + i * 8) * F + threadIdx.x] =
            (tile[threadIdx.x][threadIdx.y + i * 8] >= 0.5f) ? one : zero;
}

// ---------------- exact f16 tensor-core plane-GEMM (stacked planes in M) ----------------
// CTA tile 128(M) x 128(N), K chunk 64; 8 warps = 4(M) x 2(N), warp tile 32x64.
// 2-stage cp.async pipeline (R8 winner). smem rows 144B -> conflict-free ldmatrix.
// All pointers are group-relative (blockIdx.z = b within group).
__global__ __launch_bounds__(256, 2)
void hmma_gemm_kernel(const __half* __restrict__ A,
                      const __half* __restrict__ Bt,
                      float* __restrict__ Sh, float* __restrict__ Sr,
                      int Mhid, int Mr, int K)
{
    constexpr int ROWB  = 144;
    constexpr int BOFF  = 128 * ROWB;            // 18432
    constexpr int STAGE = 2 * BOFF;              // 36864 (A tile + B tile)

    extern __shared__ __align__(16) char smem[];
    const uint32_t uS = smem_u32(smem);

    const int tid  = threadIdx.x;
    const int wid  = tid >> 5;
    const int lane = tid & 31;
    const int wm   = wid & 3;          // warp m-group (32 rows)
    const int wn   = wid >> 2;         // warp n-group (64 cols)

    const int m0 = blockIdx.y * 128;
    const int n0 = blockIdx.x * 128;
    const int b  = blockIdx.z;

    const __half* Brow = Bt + ((size_t)b * T_LEN + n0) * K;

    const int q   = tid & 7;
    const int r0w = tid >> 3;
    const __half* Apos = A + (size_t)m0 * K + q * 8;
    const __half* Bpos = Brow + q * 8;

    const uint32_t lmoff = (uint32_t)((lane & 15) * ROWB + (lane >> 4) * 16);

    float acc[2][8][4];
#pragma unroll
    for (int ii = 0; ii < 2; ii++)
#pragma unroll
        for (int jj = 0; jj < 8; jj++)
#pragma unroll
            for (int r = 0; r < 4; r++) acc[ii][jj][r] = 0.0f;

    const int NKC = K / 64;

    auto issue = [&](int kc) {
        const uint32_t buf = uS + (uint32_t)(kc & 1) * STAGE;
        const int kB = kc * 64;
#pragma unroll
        for (int u = 0; u < 4; u++) {
            const int row = r0w + u * 32;
            cp_async16(buf + row * ROWB + q * 16, Apos + (size_t)row * K + kB);
            cp_async16(buf + BOFF + row * ROWB + q * 16, Bpos + (size_t)row * K + kB);
        }
        CP_COMMIT();
    };

    issue(0);

    for (int kc = 0; kc < NKC; kc++) {
        CP_WAIT0();
        __syncthreads();

        if (kc + 1 < NKC) issue(kc + 1);

        const uint32_t cur = uS + (uint32_t)(kc & 1) * STAGE;

#pragma unroll
        for (int ks = 0; ks < 4; ks++) {
            const uint32_t koff = cur + (uint32_t)(ks * 32) + lmoff;

            uint32_t bf[4][4];
#pragma unroll
            for (int j2 = 0; j2 < 4; j2++)
                ldsm_x4(bf[j2], koff + BOFF + (uint32_t)((wn * 64 + j2 * 16) * ROWB));

#pragma unroll
            for (int ii = 0; ii < 2; ii++) {
                uint32_t af[4];
                ldsm_x4(af, koff + (uint32_t)((wm * 32 + ii * 16) * ROWB));
#pragma unroll
                for (int j2 = 0; j2 < 4; j2++) {
                    mma_f16(acc[ii][2 * j2 + 0], af, bf[j2][0], bf[j2][2]);
                    mma_f16(acc[ii][2 * j2 + 1], af, bf[j2][1], bf[j2][3]);
                }
            }
        }
        __syncthreads();
    }

    float* dst;
    if (m0 < Mhid) dst = Sh + ((size_t)b * Mhid + m0) * T_LEN;
    else           dst = Sr + ((size_t)b * Mr + (m0 - Mhid)) * T_LEN;

#pragma unroll
    for (int ii = 0; ii < 2; ii++) {
        const int rloc = wm * 32 + ii * 16 + (lane >> 2);
        float* d0 = dst + (size_t)rloc * T_LEN + n0 + wn * 64 + (lane & 3) * 2;
#pragma unroll
        for (int jj = 0; jj < 8; jj++) {
            *(float2*)(d0 + jj * 8)             = make_float2(acc[ii][jj][0], acc[ii][jj][1]);
            *(float2*)(d0 + 8 * T_LEN + jj * 8) = make_float2(acc[ii][jj][2], acc[ii][jj][3]);
        }
    }
}

// ---------------- exact integer digit fold (no FP64) ----------------
__device__ __forceinline__ float fold3(float a, float b, float c) {
    long long q = ((long long)__float2int_rn(a) << 22)
                + ((long long)__float2int_rn(b) << 11)
                +  (long long)__float2int_rn(c);
    return (float)q * 1.16415321826934814453125e-10f;   // 2^-33 exact
}

// ---------------- LIF with integer fold + fused f16 transpose (group-relative) ----------------
__global__ __launch_bounds__(256)
void lif_fold_kernel(const float* __restrict__ S3, float* __restrict__ v_out,
                     float* __restrict__ s_out, __half* __restrict__ bTo, int layer)
{
    const int idx = blockIdx.x * blockDim.x + threadIdx.x;   // chain = b*HID + h (group-rel)
    const int b = idx / HID, h = idx % HID;
    const float4* __restrict__ p0 = (const float4*)(S3 + ((size_t)b * 3 * HID + h) * T_LEN);
    const float4* __restrict__ p1 = (const float4*)(S3 + ((size_t)b * 3 * HID + HID + h) * T_LEN);
    const float4* __restrict__ p2 = (const float4*)(S3 + ((size_t)b * 3 * HID + 2 * HID + h) * T_LEN);
    float4* __restrict__ vp4 = (float4*)(v_out + (size_t)idx * T_LEN);
    float4* __restrict__ sp4 = (float4*)(s_out + (size_t)idx * T_LEN);
    __half* __restrict__ bTp = bTo + (size_t)b * T_LEN * HID + h;

    const __half hone = __float2half(1.0f), hzero = __float2half(0.0f);
    float cur = 0.0f, volt = 0.0f;
    unsigned cnt = 0;

#pragma unroll 4
    for (int t4 = 0; t4 < T_LEN / 4; t4++) {
        const float4 a = p0[t4], bb = p1[t4], c = p2[t4];
        float4 z;
        z.x = fold3(a.x, bb.x, c.x);
        z.y = fold3(a.y, bb.y, c.y);
        z.z = fold3(a.z, bb.z, c.z);
        z.w = fold3(a.w, bb.w, c.w);
        float4 v, s;
        bool b0, b1, b2, b3;
        cur = 0.75f * cur + z.x;  volt = 0.97f * volt + cur;  v.x = volt;
        b0 = (volt >= 1.25f); s.x = b0 ? 1.0f : 0.0f; cnt += (unsigned)b0; if (b0) volt = 0.0f;
        cur = 0.75f * cur + z.y;  volt = 0.97f * volt + cur;  v.y = volt;
        b1 = (volt >= 1.25f); s.y = b1 ? 1.0f : 0.0f; cnt += (unsigned)b1; if (b1) volt = 0.0f;
        cur = 0.75f * cur + z.z;  volt = 0.97f * volt + cur;  v.z = volt;
        b2 = (volt >= 1.25f); s.z = b2 ? 1.0f : 0.0f; cnt += (unsigned)b2; if (b2) volt = 0.0f;
        cur = 0.75f * cur + z.w;  volt = 0.97f * volt + cur;  v.w = volt;
        b3 = (volt >= 1.25f); s.w = b3 ? 1.0f : 0.0f; cnt += (unsigned)b3; if (b3) volt = 0.0f;
        vp4[t4] = v;
        sp4[t4] = s;
        const int t = t4 * 4;
        bTp[(size_t)(t + 0) * HID] = b0 ? hone : hzero;
        bTp[(size_t)(t + 1) * HID] = b1 ? hone : hzero;
        bTp[(size_t)(t + 2) * HID] = b2 ? hone : hzero;
        bTp[(size_t)(t + 3) * HID] = b3 ? hone : hzero;
    }

    __shared__ unsigned red[256];
    red[threadIdx.x] = cnt;
    __syncthreads();
#pragma unroll
    for (int off = 128; off > 0; off >>= 1) {
        if (threadIdx.x < off) red[threadIdx.x] += red[threadIdx.x + off];
        __syncthreads();
    }
    if (threadIdx.x == 0)
        atomicAdd(&g_cnt[layer], (unsigned long long)red[0]);
}

// fold readout planes: Sr [gb][3*OUTD][T] -> r [gb][OUTD][T]  (group-relative)
__global__ __launch_bounds__(256)
void fold_readout_kernel(float* __restrict__ rout, const float* __restrict__ Srg)
{
    const int i = blockIdx.x * blockDim.x + threadIdx.x;
    const int per = OUTD * T_LEN / 4;
    const int b = i / per, rem = i % per;
    const float4* base = (const float4*)(Srg + (size_t)b * 3 * OUTD * T_LEN);
    const float4 a  = base[0 * per + rem];
    const float4 bb = base[1 * per + rem];
    const float4 c  = base[2 * per + rem];
    float4 r;
    r.x = fold3(a.x, bb.x, c.x);
    r.y = fold3(a.y, bb.y, c.y);
    r.z = fold3(a.z, bb.z, c.z);
    r.w = fold3(a.w, bb.w, c.w);
    ((float4*)(rout))[(size_t)b * per + rem] = r;
}

__global__ void finalize_counts_kernel(float* __restrict__ out)
{
    const double total = (double)((size_t)BATCH * HID * T_LEN);
    out[0] = (float)((double)g_cnt[0] / total);
    out[1] = (float)((double)g_cnt[1] / total);
}

// ---------------- launch ----------------
extern "C" void kernel_launch(void* const* d_in, const int* in_sizes, int n_in,
                              void* d_out, int out_size)
{
    const float* spike = (const float*)d_in[0]; // [32, 512, 256]
    const float* W1    = (const float*)d_in[1]; // [1024, 512]
    const float* W2    = (const float*)d_in[2]; // [1024, 1024]
    const float* R1    = (const float*)d_in[3]; // [128, 1024]
    const float* R2    = (const float*)d_in[4]; // [128, 1024]
    float* out = (float*)d_out;

    float *sptr, *srptr;
    __half *bTx, *bT, *w1h, *w2r1, *r2h;
    cudaGetSymbolAddress((void**)&sptr,  g_s);
    cudaGetSymbolAddress((void**)&srptr, g_sr);
    cudaGetSymbolAddress((void**)&bTx,   g_bTx);
    cudaGetSymbolAddress((void**)&bT,    g_bT);
    cudaGetSymbolAddress((void**)&w1h,   g_w1h);
    cudaGetSymbolAddress((void**)&w2r1,  g_w2r1);
    cudaGetSymbolAddress((void**)&r2h,   g_r2h);

    float* s0 = out + SOFF0;
    float* s1 = out + SOFF1;
    float* r0 = out + ROFF0;
    float* r1 = out + ROFF1;
    float* v0 = out + VOFF0;
    float* v1 = out + VOFF1;

    const int SMEM = 2 * 36864;   // 73728
    cudaFuncSetAttribute(hmma_gemm_kernel, cudaFuncAttributeMaxDynamicSharedMemorySize, SMEM);

    // ---- shared prep on the capture (legacy) stream ----
    prep_all_kernel<<<512, 256>>>(W1, W2, R1, R2, w1h, w2r1, r2h);

    // ---- fork 4 batch-group pipelines onto non-blocking streams ----
    cudaStream_t st[NGROUP];
    cudaEvent_t  evFork, evJoin[NGROUP];
    cudaEventCreateWithFlags(&evFork, cudaEventDisableTiming);
    cudaEventRecord(evFork, 0);
    for (int g = 0; g < NGROUP; g++) {
        cudaStreamCreateWithFlags(&st[g], cudaStreamNonBlocking);
        cudaEventCreateWithFlags(&evJoin[g], cudaEventDisableTiming);
        cudaStreamWaitEvent(st[g], evFork, 0);
    }

    for (int g = 0; g < NGROUP; g++) {
        const size_t bo = (size_t)g * GB;
        const float*  spike_g = spike + bo * F_IN * T_LEN;
        __half* bTx_g = bTx + bo * T_LEN * F_IN;
        __half* bT_g  = bT  + bo * T_LEN * HID;
        float*  s3_g  = sptr  + bo * 3 * HID  * T_LEN;
        float*  sr_g  = srptr + bo * 3 * OUTD * T_LEN;
        float*  v0_g = v0 + bo * HID * T_LEN;
        float*  v1_g = v1 + bo * HID * T_LEN;
        float*  s0_g = s0 + bo * HID * T_LEN;
        float*  s1_g = s1 + bo * HID * T_LEN;
        float*  r0_g = r0 + bo * OUTD * T_LEN;
        float*  r1_g = r1 + bo * OUTD * T_LEN;
        const int FOLD_BLOCKS = (GB * OUTD * T_LEN / 4) / 256;   // 256
        const int LIF_BLOCKS  = (GB * HID) / 256;                // 32

        // input spikes^T
        transpose_h_kernel<<<dim3(T_LEN / 32, F_IN / 32, GB), dim3(32, 8), 0, st[g]>>>(
            spike_g, bTx_g, F_IN);
        // layer 1 synapse plane sums (M=3072, K=512)
        hmma_gemm_kernel<<<dim3(T_LEN / 128, 3 * HID / 128, GB), 256, SMEM, st[g]>>>(
            w1h, bTx_g, s3_g, sr_g, 3 * HID, 0, F_IN);
        lif_fold_kernel<<<LIF_BLOCKS, 256, 0, st[g]>>>(s3_g, v0_g, s0_g, bT_g, 0);
        // layer 2 synapse + readout 1 stacked (M=3456, K=1024)
        hmma_gemm_kernel<<<dim3(T_LEN / 128, (3 * HID + 3 * OUTD) / 128, GB), 256, SMEM, st[g]>>>(
            w2r1, bT_g, s3_g, sr_g, 3 * HID, 3 * OUTD, HID);
        lif_fold_kernel<<<LIF_BLOCKS, 256, 0, st[g]>>>(s3_g, v1_g, s1_g, bT_g, 1);
        fold_readout_kernel<<<FOLD_BLOCKS, 256, 0, st[g]>>>(r0_g, sr_g);
        // readout 2 (M=384, K=1024)
        hmma_gemm_kernel<<<dim3(T_LEN / 128, 3 * OUTD / 128, GB), 256, SMEM, st[g]>>>(
            r2h, bT_g, s3_g, sr_g, 0, 3 * OUTD, HID);
        fold_readout_kernel<<<FOLD_BLOCKS, 256, 0, st[g]>>>(r1_g, sr_g);

        cudaEventRecord(evJoin[g], st[g]);
    }

    // ---- join and finalize on the capture stream ----
    for (int g = 0; g < NGROUP; g++)
        cudaStreamWaitEvent(0, evJoin[g], 0);
    finalize_counts_kernel<<<1, 1>>>(out + CNTOFF);

    for (int g = 0; g < NGROUP; g++) {
        cudaStreamDestroy(st[g]);
        cudaEventDestroy(evJoin[g]);
    }
    cudaEventDestroy(evFork);
}

// round 16
// speedup vs baseline: 1.3276x; 1.3276x over previous
#include <cuda_runtime.h>
#include <cuda_fp16.h>
#include <cstdint>

// Problem dims (fixed by the dataset)
#define BATCH 32
#define F_IN  512
#define T_LEN 256
#define HID   1024
#define OUTD  128

#define N_CHAINS (BATCH * HID)                  // 32768 LIF chains per layer

// Output layout (floats): spikes0, spikes1, readouts0, readouts1, voltages0, voltages1, counts[2]
#define SOFF0 ((size_t)0)
#define SOFF1 ((size_t)8388608)
#define ROFF0 ((size_t)16777216)
#define ROFF1 ((size_t)17825792)
#define VOFF0 ((size_t)18874368)
#define VOFF1 ((size_t)27262976)
#define CNTOFF ((size_t)35651584)

// ---------------- device scratch ----------------
__device__ float  g_s [(size_t)BATCH * 3 * HID  * T_LEN];    // hidden plane sums (100.7MB)
__device__ float  g_sr[(size_t)BATCH * 3 * OUTD * T_LEN];    // readout plane sums (12.6MB)
__device__ __half g_bT[(size_t)BATCH * T_LEN * HID];         // transposed f16 B operand (reused)
__device__ __half g_w1h [3 * HID * F_IN];                    // W1 digit planes
__device__ __half g_w2r1[3 * HID * HID + 3 * OUTD * HID];    // W2 planes ++ R1 planes (stacked)
__device__ __half g_r2h [3 * OUTD * HID];                    // R2 digit planes
__device__ unsigned long long g_cnt[2];

// ---------------- baseline-PTX helpers (valid on compute_103) ----------------
__device__ __forceinline__ uint32_t smem_u32(const void* p) {
    uint32_t a;
    asm("{ .reg .u64 t; cvta.to.shared.u64 t, %1; cvt.u32.u64 %0, t; }" : "=r"(a) : "l"(p));
    return a;
}

__device__ __forceinline__ void cp_async16(uint32_t dst, const void* src) {
    asm volatile("cp.async.ca.shared.global [%0], [%1], 16;" :: "r"(dst), "l"(src));
}
#define CP_COMMIT() asm volatile("cp.async.commit_group;" ::: "memory")
#define CP_WAIT0()  asm volatile("cp.async.wait_group 0;" ::: "memory")

__device__ __forceinline__ void ldsm_x4(uint32_t r[4], uint32_t addr) {
    asm volatile("ldmatrix.sync.aligned.m8n8.x4.shared.b16 {%0,%1,%2,%3}, [%4];"
        : "=r"(r[0]), "=r"(r[1]), "=r"(r[2]), "=r"(r[3]) : "r"(addr));
}

// f16 MMA with f32 accumulate. Exact for small-integer operands (all sums < 2^24).
__device__ __forceinline__ void mma_f16(float* d, const uint32_t* a, uint32_t b0, uint32_t b1) {
    asm volatile(
        "mma.sync.aligned.m16n8k16.row.col.f32.f16.f16.f32 "
        "{%0,%1,%2,%3}, {%4,%5,%6,%7}, {%8,%9}, {%0,%1,%2,%3};"
        : "+f"(d[0]), "+f"(d[1]), "+f"(d[2]), "+f"(d[3])
        : "r"(a[0]), "r"(a[1]), "r"(a[2]), "r"(a[3]), "r"(b0), "r"(b1));
}

// ---------------- combined prep kernel ----------------
// Exact 3-digit balanced base-2048 fixed-point split at scale 2^33 for ALL four
// weight matrices in one launch; also zeroes the spike counters.
__device__ __forceinline__ void wsplit(const float* __restrict__ W, __half* __restrict__ out,
                                       int i, int n) {
    double wd = (double)W[i] * 8589934592.0;   // 2^33, exact
    long long q = llrint(wd);
    long long c0 = (q + (1LL << 21)) >> 22;
    long long r  = q - (c0 << 22);
    long long c1 = (r + (1LL << 10)) >> 11;
    long long c2 = r - (c1 << 11);
    out[i]         = __int2half_rn((int)c0);
    out[n + i]     = __int2half_rn((int)c1);
    out[2 * n + i] = __int2half_rn((int)c2);
}

__global__ void prep_all_kernel(const float* __restrict__ W1, const float* __restrict__ W2,
                                const float* __restrict__ R1, const float* __restrict__ R2,
                                __half* __restrict__ w1h, __half* __restrict__ w2r1,
                                __half* __restrict__ r2h) {
    const int n1 = HID * F_IN;            // 524288
    const int n2 = HID * HID;             // 1048576
    const int n3 = OUTD * HID;            // 131072
    const int NTOT = n1 + n2 + 2 * n3;    // 1835008
    int gid = blockIdx.x * blockDim.x + threadIdx.x;
    if (gid == 0) { g_cnt[0] = 0ull; g_cnt[1] = 0ull; }
    for (int i = gid; i < NTOT; i += gridDim.x * blockDim.x) {
        if (i < n1)                wsplit(W1, w1h, i, n1);
        else if (i < n1 + n2)      wsplit(W2, w2r1, i - n1, n2);
        else if (i < n1 + n2 + n3) wsplit(R1, w2r1 + 3 * n2, i - n1 - n2, n3);
        else                       wsplit(R2, r2h, i - n1 - n2 - n3, n3);
    }
}

// in: fp32 [B, F, T] (values exactly 0/1) -> out: f16 [B, T, F]  (input spikes only)
__global__ void transpose_h_kernel(const float* __restrict__ in,
                                   __half* __restrict__ outT, int F) {
    __shared__ float tile[32][33];
    const int b = blockIdx.z;
    const int t0 = blockIdx.x * 32, f0 = blockIdx.y * 32;
    const float* inp = in + ((size_t)b * F + f0) * T_LEN + t0;
#pragma unroll
    for (int i = 0; i < 4; i++)
        tile[threadIdx.y + i * 8][threadIdx.x] = inp[(size_t)(threadIdx.y + i * 8) * T_LEN + threadIdx.x];
    __syncthreads();
    __half* op = outT + ((size_t)b * T_LEN + t0) * F + f0;
    const __half one = __float2half(1.0f), zero = __float2half(0.0f);
#pragma unroll
    for (int i = 0; i < 4; i++)
        op[(size_t)(threadIdx.y + i * 8) * F + threadIdx.x] =
            (tile[threadIdx.x][threadIdx.y + i * 8] >= 0.5f) ? one : zero;
}

// ---------------- exact f16 tensor-core plane-GEMM (stacked planes in M) ----------------
// CTA tile 128(M) x 128(N), K chunk 64; 8 warps = 4(M) x 2(N), warp tile 32x64.
// 2-stage cp.async pipeline (R8 winner). smem rows 144B -> conflict-free ldmatrix.
__global__ __launch_bounds__(256, 2)
void hmma_gemm_kernel(const __half* __restrict__ A,
                      const __half* __restrict__ Bt,
                      float* __restrict__ Sh, float* __restrict__ Sr,
                      int Mhid, int Mr, int K)
{
    constexpr int ROWB  = 144;
    constexpr int BOFF  = 128 * ROWB;            // 18432
    constexpr int STAGE = 2 * BOFF;              // 36864 (A tile + B tile)

    extern __shared__ __align__(16) char smem[];
    const uint32_t uS = smem_u32(smem);

    const int tid  = threadIdx.x;
    const int wid  = tid >> 5;
    const int lane = tid & 31;
    const int wm   = wid & 3;          // warp m-group (32 rows)
    const int wn   = wid >> 2;         // warp n-group (64 cols)

    const int m0 = blockIdx.y * 128;
    const int n0 = blockIdx.x * 128;
    const int b  = blockIdx.z;

    const __half* Brow = Bt + ((size_t)b * T_LEN + n0) * K;

    const int q   = tid & 7;
    const int r0w = tid >> 3;
    const __half* Apos = A + (size_t)m0 * K + q * 8;
    const __half* Bpos = Brow + q * 8;

    const uint32_t lmoff = (uint32_t)((lane & 15) * ROWB + (lane >> 4) * 16);

    float acc[2][8][4];
#pragma unroll
    for (int ii = 0; ii < 2; ii++)
#pragma unroll
        for (int jj = 0; jj < 8; jj++)
#pragma unroll
            for (int r = 0; r < 4; r++) acc[ii][jj][r] = 0.0f;

    const int NKC = K / 64;

    auto issue = [&](int kc) {
        const uint32_t buf = uS + (uint32_t)(kc & 1) * STAGE;
        const int kB = kc * 64;
#pragma unroll
        for (int u = 0; u < 4; u++) {
            const int row = r0w + u * 32;
            cp_async16(buf + row * ROWB + q * 16, Apos + (size_t)row * K + kB);
            cp_async16(buf + BOFF + row * ROWB + q * 16, Bpos + (size_t)row * K + kB);
        }
        CP_COMMIT();
    };

    issue(0);

    for (int kc = 0; kc < NKC; kc++) {
        CP_WAIT0();
        __syncthreads();

        if (kc + 1 < NKC) issue(kc + 1);

        const uint32_t cur = uS + (uint32_t)(kc & 1) * STAGE;

#pragma unroll
        for (int ks = 0; ks < 4; ks++) {
            const uint32_t koff = cur + (uint32_t)(ks * 32) + lmoff;

            uint32_t bf[4][4];
#pragma unroll
            for (int j2 = 0; j2 < 4; j2++)
                ldsm_x4(bf[j2], koff + BOFF + (uint32_t)((wn * 64 + j2 * 16) * ROWB));

#pragma unroll
            for (int ii = 0; ii < 2; ii++) {
                uint32_t af[4];
                ldsm_x4(af, koff + (uint32_t)((wm * 32 + ii * 16) * ROWB));
#pragma unroll
                for (int j2 = 0; j2 < 4; j2++) {
                    mma_f16(acc[ii][2 * j2 + 0], af, bf[j2][0], bf[j2][2]);
                    mma_f16(acc[ii][2 * j2 + 1], af, bf[j2][1], bf[j2][3]);
                }
            }
        }
        __syncthreads();
    }

    float* dst;
    if (m0 < Mhid) dst = Sh + ((size_t)b * Mhid + m0) * T_LEN;
    else           dst = Sr + ((size_t)b * Mr + (m0 - Mhid)) * T_LEN;

#pragma unroll
    for (int ii = 0; ii < 2; ii++) {
        const int rloc = wm * 32 + ii * 16 + (lane >> 2);
        float* d0 = dst + (size_t)rloc * T_LEN + n0 + wn * 64 + (lane & 3) * 2;
#pragma unroll
        for (int jj = 0; jj < 8; jj++) {
            *(float2*)(d0 + jj * 8)             = make_float2(acc[ii][jj][0], acc[ii][jj][1]);
            *(float2*)(d0 + 8 * T_LEN + jj * 8) = make_float2(acc[ii][jj][2], acc[ii][jj][3]);
        }
    }
}

// ---------------- exact integer digit fold (no FP64) ----------------
// Plane sums are exact integers |.| <= 2^20 (fp32-exact). q = i0*2^22 + i1*2^11 + i2
// is exact in int64; cvt.rn.f32.s64 rounds once; *2^-33f is exact (power of two).
__device__ __forceinline__ float fold3(float a, float b, float c) {
    long long q = ((long long)__float2int_rn(a) << 22)
                + ((long long)__float2int_rn(b) << 11)
                +  (long long)__float2int_rn(c);
    return (float)q * 1.16415321826934814453125e-10f;   // 2^-33 exact
}

// ---------------- LIF: integer fold + fused f16 transpose + load prefetch ----------------
// Latency-bound (R15 evidence: runtime ~independent of grid size). Double-buffer the
// three plane loads: issue t4+1's loads before computing t4's 4 recurrence steps,
// so the ~600-cycle gmem latency overlaps the compute+store of the current group.
__global__ __launch_bounds__(256)
void lif_fold_kernel(float* __restrict__ v_out, float* __restrict__ s_out, int layer)
{
    const int idx = blockIdx.x * blockDim.x + threadIdx.x;   // chain = b*HID + h
    const int b = idx / HID, h = idx % HID;
    const float4* __restrict__ p0 = (const float4*)(g_s + ((size_t)b * 3 * HID + h) * T_LEN);
    const float4* __restrict__ p1 = (const float4*)(g_s + ((size_t)b * 3 * HID + HID + h) * T_LEN);
    const float4* __restrict__ p2 = (const float4*)(g_s + ((size_t)b * 3 * HID + 2 * HID + h) * T_LEN);
    float4* __restrict__ vp4 = (float4*)(v_out + (size_t)idx * T_LEN);
    float4* __restrict__ sp4 = (float4*)(s_out + (size_t)idx * T_LEN);
    __half* __restrict__ bTp = g_bT + (size_t)b * T_LEN * HID + h;   // stride HID per t

    const __half hone = __float2half(1.0f), hzero = __float2half(0.0f);
    float cur = 0.0f, volt = 0.0f;
    unsigned cnt = 0;

    // prefetch t4 = 0
    float4 a = p0[0], bb = p1[0], c = p2[0];

#pragma unroll 4
    for (int t4 = 0; t4 < T_LEN / 4; t4++) {
        // issue next group's loads early (overlap with compute below)
        float4 an, bn, cn;
        if (t4 + 1 < T_LEN / 4) {
            an = p0[t4 + 1]; bn = p1[t4 + 1]; cn = p2[t4 + 1];
        }

        float4 z;
        z.x = fold3(a.x, bb.x, c.x);
        z.y = fold3(a.y, bb.y, c.y);
        z.z = fold3(a.z, bb.z, c.z);
        z.w = fold3(a.w, bb.w, c.w);
        float4 v, s;
        bool b0, b1, b2, b3;
        cur = 0.75f * cur + z.x;  volt = 0.97f * volt + cur;  v.x = volt;
        b0 = (volt >= 1.25f); s.x = b0 ? 1.0f : 0.0f; cnt += (unsigned)b0; if (b0) volt = 0.0f;
        cur = 0.75f * cur + z.y;  volt = 0.97f * volt + cur;  v.y = volt;
        b1 = (volt >= 1.25f); s.y = b1 ? 1.0f : 0.0f; cnt += (unsigned)b1; if (b1) volt = 0.0f;
        cur = 0.75f * cur + z.z;  volt = 0.97f * volt + cur;  v.z = volt;
        b2 = (volt >= 1.25f); s.z = b2 ? 1.0f : 0.0f; cnt += (unsigned)b2; if (b2) volt = 0.0f;
        cur = 0.75f * cur + z.w;  volt = 0.97f * volt + cur;  v.w = volt;
        b3 = (volt >= 1.25f); s.w = b3 ? 1.0f : 0.0f; cnt += (unsigned)b3; if (b3) volt = 0.0f;
        vp4[t4] = v;
        sp4[t4] = s;
        // fused transpose: coalesced across threads (consecutive h) at each t
        const int t = t4 * 4;
        bTp[(size_t)(t + 0) * HID] = b0 ? hone : hzero;
        bTp[(size_t)(t + 1) * HID] = b1 ? hone : hzero;
        bTp[(size_t)(t + 2) * HID] = b2 ? hone : hzero;
        bTp[(size_t)(t + 3) * HID] = b3 ? hone : hzero;

        a = an; bb = bn; c = cn;
    }

    __shared__ unsigned red[256];
    red[threadIdx.x] = cnt;
    __syncthreads();
#pragma unroll
    for (int off = 128; off > 0; off >>= 1) {
        if (threadIdx.x < off) red[threadIdx.x] += red[threadIdx.x + off];
        __syncthreads();
    }
    if (threadIdx.x == 0)
        atomicAdd(&g_cnt[layer], (unsigned long long)red[0]);
}

// fold readout planes: Sr [B][3*OUTD][T] -> r [B][OUTD][T]
__global__ __launch_bounds__(256)
void fold_readout_kernel(float* __restrict__ rout)
{
    const int i = blockIdx.x * blockDim.x + threadIdx.x;   // over B*OUTD*T/4
    const int per = OUTD * T_LEN / 4;
    const int b = i / per, rem = i % per;
    const float4* base = (const float4*)(g_sr + (size_t)b * 3 * OUTD * T_LEN);
    const float4 a  = base[0 * per + rem];
    const float4 bb = base[1 * per + rem];
    const float4 c  = base[2 * per + rem];
    float4 r;
    r.x = fold3(a.x, bb.x, c.x);
    r.y = fold3(a.y, bb.y, c.y);
    r.z = fold3(a.z, bb.z, c.z);
    r.w = fold3(a.w, bb.w, c.w);
    ((float4*)(rout + (size_t)b * OUTD * T_LEN))[rem] = r;
}

__global__ void finalize_counts_kernel(float* __restrict__ out)
{
    const double total = (double)((size_t)BATCH * HID * T_LEN);
    out[0] = (float)((double)g_cnt[0] / total);
    out[1] = (float)((double)g_cnt[1] / total);
}

// ---------------- launch ----------------
extern "C" void kernel_launch(void* const* d_in, const int* in_sizes, int n_in,
                              void* d_out, int out_size)
{
    const float* spike = (const float*)d_in[0]; // [32, 512, 256]
    const float* W1    = (const float*)d_in[1]; // [1024, 512]
    const float* W2    = (const float*)d_in[2]; // [1024, 1024]
    const float* R1    = (const float*)d_in[3]; // [128, 1024]
    const float* R2    = (const float*)d_in[4]; // [128, 1024]
    float* out = (float*)d_out;

    float *sptr, *srptr;
    __half *bT, *w1h, *w2r1, *r2h;
    cudaGetSymbolAddress((void**)&sptr,  g_s);
    cudaGetSymbolAddress((void**)&srptr, g_sr);
    cudaGetSymbolAddress((void**)&bT,    g_bT);
    cudaGetSymbolAddress((void**)&w1h,   g_w1h);
    cudaGetSymbolAddress((void**)&w2r1,  g_w2r1);
    cudaGetSymbolAddress((void**)&r2h,   g_r2h);

    float* s0 = out + SOFF0;
    float* s1 = out + SOFF1;
    float* r0 = out + ROFF0;
    float* r1 = out + ROFF1;
    float* v0 = out + VOFF0;
    float* v1 = out + VOFF1;

    const int SMEM = 2 * 36864;   // 73728 (2-stage pipeline, R8 winner)
    cudaFuncSetAttribute(hmma_gemm_kernel, cudaFuncAttributeMaxDynamicSharedMemorySize, SMEM);

    // All weight digit planes + counter init in one launch
    prep_all_kernel<<<512, 256>>>(W1, W2, R1, R2, w1h, w2r1, r2h);

    // x^T f16 (input spikes only; s0/s1 transposes are fused into LIF)
    transpose_h_kernel<<<dim3(T_LEN / 32, F_IN / 32, BATCH), dim3(32, 8)>>>(spike, bT, F_IN);

    // Layer 1 synapse plane sums: S = W1planes @ x  (M=3072, K=512)
    hmma_gemm_kernel<<<dim3(T_LEN / 128, 3 * HID / 128, BATCH), 256, SMEM>>>(
        w1h, bT, sptr, srptr, 3 * HID, 0, F_IN);
    lif_fold_kernel<<<N_CHAINS / 256, 256>>>(v0, s0, 0);   // also writes s0^T f16 to bT

    // Layer 2 synapse + readout 1 in ONE stacked GEMM (M = 3072 + 384 = 3456, K=1024)
    hmma_gemm_kernel<<<dim3(T_LEN / 128, (3 * HID + 3 * OUTD) / 128, BATCH), 256, SMEM>>>(
        w2r1, bT, sptr, srptr, 3 * HID, 3 * OUTD, HID);

    lif_fold_kernel<<<N_CHAINS / 256, 256>>>(v1, s1, 1);   // also writes s1^T f16 to bT
    fold_readout_kernel<<<(BATCH * OUTD * T_LEN / 4) / 256, 256>>>(r0);

    // readout 2 (M=384, K=1024)
    hmma_gemm_kernel<<<dim3(T_LEN / 128, 3 * OUTD / 128, BATCH), 256, SMEM>>>(
        r2h, bT, sptr, srptr, 0, 3 * OUTD, HID);
    fold_readout_kernel<<<(BATCH * OUTD * T_LEN / 4) / 256, 256>>>(r1);

    finalize_counts_kernel<<<1, 1>>>(out + CNTOFF);
}

// round 17
// speedup vs baseline: 1.4134x; 1.0646x over previous
#include <cuda_runtime.h>
#include <cuda_fp16.h>
#include <cstdint>

// Problem dims (fixed by the dataset)
#define BATCH 32
#define F_IN  512
#define T_LEN 256
#define HID   1024
#define OUTD  128

#define N_CHAINS (BATCH * HID)                  // 32768 LIF chains per layer

// Output layout (floats): spikes0, spikes1, readouts0, readouts1, voltages0, voltages1, counts[2]
#define SOFF0 ((size_t)0)
#define SOFF1 ((size_t)8388608)
#define ROFF0 ((size_t)16777216)
#define ROFF1 ((size_t)17825792)
#define VOFF0 ((size_t)18874368)
#define VOFF1 ((size_t)27262976)
#define CNTOFF ((size_t)35651584)

// ---------------- device scratch ----------------
__device__ float  g_s [(size_t)BATCH * 3 * HID  * T_LEN];    // hidden plane sums (100.7MB)
__device__ float  g_sr[(size_t)BATCH * 2 * OUTD * T_LEN];    // readout plane sums (2 planes)
__device__ __half g_bT[(size_t)BATCH * T_LEN * HID];         // transposed f16 B operand (reused)
__device__ __half g_w1h [3 * HID * F_IN];                    // W1 digit planes (3)
__device__ __half g_w2r1[3 * HID * HID + 2 * OUTD * HID];    // W2 planes(3) ++ R1 planes(2)
__device__ __half g_r2h [2 * OUTD * HID];                    // R2 digit planes (2)
__device__ unsigned long long g_cnt[2];

// ---------------- baseline-PTX helpers (valid on compute_103) ----------------
__device__ __forceinline__ uint32_t smem_u32(const void* p) {
    uint32_t a;
    asm("{ .reg .u64 t; cvta.to.shared.u64 t, %1; cvt.u32.u64 %0, t; }" : "=r"(a) : "l"(p));
    return a;
}

__device__ __forceinline__ void cp_async16(uint32_t dst, const void* src) {
    asm volatile("cp.async.ca.shared.global [%0], [%1], 16;" :: "r"(dst), "l"(src));
}
#define CP_COMMIT() asm volatile("cp.async.commit_group;" ::: "memory")
#define CP_WAIT0()  asm volatile("cp.async.wait_group 0;" ::: "memory")

__device__ __forceinline__ void ldsm_x4(uint32_t r[4], uint32_t addr) {
    asm volatile("ldmatrix.sync.aligned.m8n8.x4.shared.b16 {%0,%1,%2,%3}, [%4];"
        : "=r"(r[0]), "=r"(r[1]), "=r"(r[2]), "=r"(r[3]) : "r"(addr));
}

// f16 MMA with f32 accumulate. Exact for small-integer operands (all sums < 2^24).
__device__ __forceinline__ void mma_f16(float* d, const uint32_t* a, uint32_t b0, uint32_t b1) {
    asm volatile(
        "mma.sync.aligned.m16n8k16.row.col.f32.f16.f16.f32 "
        "{%0,%1,%2,%3}, {%4,%5,%6,%7}, {%8,%9}, {%0,%1,%2,%3};"
        : "+f"(d[0]), "+f"(d[1]), "+f"(d[2]), "+f"(d[3])
        : "r"(a[0]), "r"(a[1]), "r"(a[2]), "r"(a[3]), "r"(b0), "r"(b1));
}

// ---------------- combined prep kernel ----------------
// W1/W2: exact 3-digit base-2048 split at scale 2^33 (hidden layers feed a threshold).
// R1/R2: 2-digit base-2048 split at scale 2^22 (readouts: 1e-6 rel error, tolerance 1e-3).
__device__ __forceinline__ void wsplit3(const float* __restrict__ W, __half* __restrict__ out,
                                        int i, int n) {
    double wd = (double)W[i] * 8589934592.0;   // 2^33, exact
    long long q = llrint(wd);
    long long c0 = (q + (1LL << 21)) >> 22;
    long long r  = q - (c0 << 22);
    long long c1 = (r + (1LL << 10)) >> 11;
    long long c2 = r - (c1 << 11);
    out[i]         = __int2half_rn((int)c0);
    out[n + i]     = __int2half_rn((int)c1);
    out[2 * n + i] = __int2half_rn((int)c2);
}

__device__ __forceinline__ void wsplit2(const float* __restrict__ W, __half* __restrict__ out,
                                        int i, int n) {
    double wd = (double)W[i] * 4194304.0;      // 2^22, exact
    long long q = llrint(wd);
    long long c0 = (q + 1024) >> 11;
    long long c1 = q - (c0 << 11);
    out[i]     = __int2half_rn((int)c0);
    out[n + i] = __int2half_rn((int)c1);
}

__global__ void prep_all_kernel(const float* __restrict__ W1, const float* __restrict__ W2,
                                const float* __restrict__ R1, const float* __restrict__ R2,
                                __half* __restrict__ w1h, __half* __restrict__ w2r1,
                                __half* __restrict__ r2h) {
    const int n1 = HID * F_IN;            // 524288
    const int n2 = HID * HID;             // 1048576
    const int n3 = OUTD * HID;            // 131072
    const int NTOT = n1 + n2 + 2 * n3;    // 1835008
    int gid = blockIdx.x * blockDim.x + threadIdx.x;
    if (gid == 0) { g_cnt[0] = 0ull; g_cnt[1] = 0ull; }
    for (int i = gid; i < NTOT; i += gridDim.x * blockDim.x) {
        if (i < n1)                wsplit3(W1, w1h, i, n1);
        else if (i < n1 + n2)      wsplit3(W2, w2r1, i - n1, n2);
        else if (i < n1 + n2 + n3) wsplit2(R1, w2r1 + 3 * n2, i - n1 - n2, n3);
        else                       wsplit2(R2, r2h, i - n1 - n2 - n3, n3);
    }
}

// in: fp32 [B, F, T] (values exactly 0/1) -> out: f16 [B, T, F]  (input spikes only)
__global__ void transpose_h_kernel(const float* __restrict__ in,
                                   __half* __restrict__ outT, int F) {
    __shared__ float tile[32][33];
    const int b = blockIdx.z;
    const int t0 = blockIdx.x * 32, f0 = blockIdx.y * 32;
    const float* inp = in + ((size_t)b * F + f0) * T_LEN + t0;
#pragma unroll
    for (int i = 0; i < 4; i++)
        tile[threadIdx.y + i * 8][threadIdx.x] = inp[(size_t)(threadIdx.y + i * 8) * T_LEN + threadIdx.x];
    __syncthreads();
    __half* op = outT + ((size_t)b * T_LEN + t0) * F + f0;
    const __half one = __float2half(1.0f), zero = __float2half(0.0f);
#pragma unroll
    for (int i = 0; i < 4; i++)
        op[(size_t)(threadIdx.y + i * 8) * F + threadIdx.x] =
            (tile[threadIdx.x][threadIdx.y + i * 8] >= 0.5f) ? one : zero;
}

// ---------------- exact f16 tensor-core plane-GEMM (stacked planes in M) ----------------
// CTA tile 128(M) x 128(N), K chunk 64; 8 warps = 4(M) x 2(N), warp tile 32x64.
// 2-stage cp.async pipeline (R8 winner). smem rows 144B -> conflict-free ldmatrix.
__global__ __launch_bounds__(256, 2)
void hmma_gemm_kernel(const __half* __restrict__ A,
                      const __half* __restrict__ Bt,
                      float* __restrict__ Sh, float* __restrict__ Sr,
                      int Mhid, int Mr, int K)
{
    constexpr int ROWB  = 144;
    constexpr int BOFF  = 128 * ROWB;            // 18432
    constexpr int STAGE = 2 * BOFF;              // 36864 (A tile + B tile)

    extern __shared__ __align__(16) char smem[];
    const uint32_t uS = smem_u32(smem);

    const int tid  = threadIdx.x;
    const int wid  = tid >> 5;
    const int lane = tid & 31;
    const int wm   = wid & 3;          // warp m-group (32 rows)
    const int wn   = wid >> 2;         // warp n-group (64 cols)

    const int m0 = blockIdx.y * 128;
    const int n0 = blockIdx.x * 128;
    const int b  = blockIdx.z;

    const __half* Brow = Bt + ((size_t)b * T_LEN + n0) * K;

    const int q   = tid & 7;
    const int r0w = tid >> 3;
    const __half* Apos = A + (size_t)m0 * K + q * 8;
    const __half* Bpos = Brow + q * 8;

    const uint32_t lmoff = (uint32_t)((lane & 15) * ROWB + (lane >> 4) * 16);

    float acc[2][8][4];
#pragma unroll
    for (int ii = 0; ii < 2; ii++)
#pragma unroll
        for (int jj = 0; jj < 8; jj++)
#pragma unroll
            for (int r = 0; r < 4; r++) acc[ii][jj][r] = 0.0f;

    const int NKC = K / 64;

    auto issue = [&](int kc) {
        const uint32_t buf = uS + (uint32_t)(kc & 1) * STAGE;
        const int kB = kc * 64;
#pragma unroll
        for (int u = 0; u < 4; u++) {
            const int row = r0w + u * 32;
            cp_async16(buf + row * ROWB + q * 16, Apos + (size_t)row * K + kB);
            cp_async16(buf + BOFF + row * ROWB + q * 16, Bpos + (size_t)row * K + kB);
        }
        CP_COMMIT();
    };

    issue(0);

    for (int kc = 0; kc < NKC; kc++) {
        CP_WAIT0();
        __syncthreads();

        if (kc + 1 < NKC) issue(kc + 1);

        const uint32_t cur = uS + (uint32_t)(kc & 1) * STAGE;

#pragma unroll
        for (int ks = 0; ks < 4; ks++) {
            const uint32_t koff = cur + (uint32_t)(ks * 32) + lmoff;

            uint32_t bf[4][4];
#pragma unroll
            for (int j2 = 0; j2 < 4; j2++)
                ldsm_x4(bf[j2], koff + BOFF + (uint32_t)((wn * 64 + j2 * 16) * ROWB));

#pragma unroll
            for (int ii = 0; ii < 2; ii++) {
                uint32_t af[4];
                ldsm_x4(af, koff + (uint32_t)((wm * 32 + ii * 16) * ROWB));
#pragma unroll
                for (int j2 = 0; j2 < 4; j2++) {
                    mma_f16(acc[ii][2 * j2 + 0], af, bf[j2][0], bf[j2][2]);
                    mma_f16(acc[ii][2 * j2 + 1], af, bf[j2][1], bf[j2][3]);
                }
            }
        }
        __syncthreads();
    }

    float* dst;
    if (m0 < Mhid) dst = Sh + ((size_t)b * Mhid + m0) * T_LEN;
    else           dst = Sr + ((size_t)b * Mr + (m0 - Mhid)) * T_LEN;

#pragma unroll
    for (int ii = 0; ii < 2; ii++) {
        const int rloc = wm * 32 + ii * 16 + (lane >> 2);
        float* d0 = dst + (size_t)rloc * T_LEN + n0 + wn * 64 + (lane & 3) * 2;
#pragma unroll
        for (int jj = 0; jj < 8; jj++) {
            *(float2*)(d0 + jj * 8)             = make_float2(acc[ii][jj][0], acc[ii][jj][1]);
            *(float2*)(d0 + 8 * T_LEN + jj * 8) = make_float2(acc[ii][jj][2], acc[ii][jj][3]);
        }
    }
}

// ---------------- exact integer digit folds (no FP64) ----------------
__device__ __forceinline__ float fold3(float a, float b, float c) {
    long long q = ((long long)__float2int_rn(a) << 22)
                + ((long long)__float2int_rn(b) << 11)
                +  (long long)__float2int_rn(c);
    return (float)q * 1.16415321826934814453125e-10f;   // 2^-33 exact
}

__device__ __forceinline__ float fold2(float a, float b) {
    long long q = ((long long)__float2int_rn(a) << 11)
                +  (long long)__float2int_rn(b);
    return (float)q * 2.384185791015625e-7f;            // 2^-22 exact
}

// ---------------- LIF: integer fold + fused f16 transpose + depth-2 prefetch ----------------
// Latency-bound; triple-buffer the plane loads (MLP 3 -> 6 per thread).
__global__ __launch_bounds__(256)
void lif_fold_kernel(float* __restrict__ v_out, float* __restrict__ s_out, int layer)
{
    const int idx = blockIdx.x * blockDim.x + threadIdx.x;   // chain = b*HID + h
    const int b = idx / HID, h = idx % HID;
    const float4* __restrict__ p0 = (const float4*)(g_s + ((size_t)b * 3 * HID + h) * T_LEN);
    const float4* __restrict__ p1 = (const float4*)(g_s + ((size_t)b * 3 * HID + HID + h) * T_LEN);
    const float4* __restrict__ p2 = (const float4*)(g_s + ((size_t)b * 3 * HID + 2 * HID + h) * T_LEN);
    float4* __restrict__ vp4 = (float4*)(v_out + (size_t)idx * T_LEN);
    float4* __restrict__ sp4 = (float4*)(s_out + (size_t)idx * T_LEN);
    __half* __restrict__ bTp = g_bT + (size_t)b * T_LEN * HID + h;   // stride HID per t

    const __half hone = __float2half(1.0f), hzero = __float2half(0.0f);
    float cur = 0.0f, volt = 0.0f;
    unsigned cnt = 0;

    // prefetch t4 = 0, 1
    float4 a0 = p0[0], b0v = p1[0], c0v = p2[0];
    float4 a1 = p0[1], b1v = p1[1], c1v = p2[1];

#pragma unroll 4
    for (int t4 = 0; t4 < T_LEN / 4; t4++) {
        // issue loads two groups ahead (overlap with compute of this group)
        float4 a2, b2v, c2v;
        if (t4 + 2 < T_LEN / 4) {
            a2 = p0[t4 + 2]; b2v = p1[t4 + 2]; c2v = p2[t4 + 2];
        }

        float4 z;
        z.x = fold3(a0.x, b0v.x, c0v.x);
        z.y = fold3(a0.y, b0v.y, c0v.y);
        z.z = fold3(a0.z, b0v.z, c0v.z);
        z.w = fold3(a0.w, b0v.w, c0v.w);
        float4 v, s;
        bool s0b, s1b, s2b, s3b;
        cur = 0.75f * cur + z.x;  volt = 0.97f * volt + cur;  v.x = volt;
        s0b = (volt >= 1.25f); s.x = s0b ? 1.0f : 0.0f; cnt += (unsigned)s0b; if (s0b) volt = 0.0f;
        cur = 0.75f * cur + z.y;  volt = 0.97f * volt + cur;  v.y = volt;
        s1b = (volt >= 1.25f); s.y = s1b ? 1.0f : 0.0f; cnt += (unsigned)s1b; if (s1b) volt = 0.0f;
        cur = 0.75f * cur + z.z;  volt = 0.97f * volt + cur;  v.z = volt;
        s2b = (volt >= 1.25f); s.z = s2b ? 1.0f : 0.0f; cnt += (unsigned)s2b; if (s2b) volt = 0.0f;
        cur = 0.75f * cur + z.w;  volt = 0.97f * volt + cur;  v.w = volt;
        s3b = (volt >= 1.25f); s.w = s3b ? 1.0f : 0.0f; cnt += (unsigned)s3b; if (s3b) volt = 0.0f;
        vp4[t4] = v;
        sp4[t4] = s;
        // fused transpose: coalesced across threads (consecutive h) at each t
        const int t = t4 * 4;
        bTp[(size_t)(t + 0) * HID] = s0b ? hone : hzero;
        bTp[(size_t)(t + 1) * HID] = s1b ? hone : hzero;
        bTp[(size_t)(t + 2) * HID] = s2b ? hone : hzero;
        bTp[(size_t)(t + 3) * HID] = s3b ? hone : hzero;

        a0 = a1; b0v = b1v; c0v = c1v;
        a1 = a2; b1v = b2v; c1v = c2v;
    }

    __shared__ unsigned red[256];
    red[threadIdx.x] = cnt;
    __syncthreads();
#pragma unroll
    for (int off = 128; off > 0; off >>= 1) {
        if (threadIdx.x < off) red[threadIdx.x] += red[threadIdx.x + off];
        __syncthreads();
    }
    if (threadIdx.x == 0)
        atomicAdd(&g_cnt[layer], (unsigned long long)red[0]);
}

// fold readout planes: Sr [B][2*OUTD][T] -> r [B][OUTD][T]
__global__ __launch_bounds__(256)
void fold_readout_kernel(float* __restrict__ rout)
{
    const int i = blockIdx.x * blockDim.x + threadIdx.x;   // over B*OUTD*T/4
    const int per = OUTD * T_LEN / 4;
    const int b = i / per, rem = i % per;
    const float4* base = (const float4*)(g_sr + (size_t)b * 2 * OUTD * T_LEN);
    const float4 a  = base[0 * per + rem];
    const float4 bb = base[1 * per + rem];
    float4 r;
    r.x = fold2(a.x, bb.x);
    r.y = fold2(a.y, bb.y);
    r.z = fold2(a.z, bb.z);
    r.w = fold2(a.w, bb.w);
    ((float4*)(rout + (size_t)b * OUTD * T_LEN))[rem] = r;
}

__global__ void finalize_counts_kernel(float* __restrict__ out)
{
    const double total = (double)((size_t)BATCH * HID * T_LEN);
    out[0] = (float)((double)g_cnt[0] / total);
    out[1] = (float)((double)g_cnt[1] / total);
}

// ---------------- launch ----------------
extern "C" void kernel_launch(void* const* d_in, const int* in_sizes, int n_in,
                              void* d_out, int out_size)
{
    const float* spike = (const float*)d_in[0]; // [32, 512, 256]
    const float* W1    = (const float*)d_in[1]; // [1024, 512]
    const float* W2    = (const float*)d_in[2]; // [1024, 1024]
    const float* R1    = (const float*)d_in[3]; // [128, 1024]
    const float* R2    = (const float*)d_in[4]; // [128, 1024]
    float* out = (float*)d_out;

    float *sptr, *srptr;
    __half *bT, *w1h, *w2r1, *r2h;
    cudaGetSymbolAddress((void**)&sptr,  g_s);
    cudaGetSymbolAddress((void**)&srptr, g_sr);
    cudaGetSymbolAddress((void**)&bT,    g_bT);
    cudaGetSymbolAddress((void**)&w1h,   g_w1h);
    cudaGetSymbolAddress((void**)&w2r1,  g_w2r1);
    cudaGetSymbolAddress((void**)&r2h,   g_r2h);

    float* s0 = out + SOFF0;
    float* s1 = out + SOFF1;
    float* r0 = out + ROFF0;
    float* r1 = out + ROFF1;
    float* v0 = out + VOFF0;
    float* v1 = out + VOFF1;

    const int SMEM = 2 * 36864;   // 73728 (2-stage pipeline, R8 winner)
    cudaFuncSetAttribute(hmma_gemm_kernel, cudaFuncAttributeMaxDynamicSharedMemorySize, SMEM);

    // All weight digit planes + counter init in one launch
    prep_all_kernel<<<512, 256>>>(W1, W2, R1, R2, w1h, w2r1, r2h);

    // x^T f16 (input spikes only; s0/s1 transposes are fused into LIF)
    transpose_h_kernel<<<dim3(T_LEN / 32, F_IN / 32, BATCH), dim3(32, 8)>>>(spike, bT, F_IN);

    // Layer 1 synapse plane sums: S = W1planes @ x  (M=3072, K=512)
    hmma_gemm_kernel<<<dim3(T_LEN / 128, 3 * HID / 128, BATCH), 256, SMEM>>>(
        w1h, bT, sptr, srptr, 3 * HID, 0, F_IN);
    lif_fold_kernel<<<N_CHAINS / 256, 256>>>(v0, s0, 0);   // also writes s0^T f16 to bT

    // Layer 2 synapse + readout 1 in ONE stacked GEMM (M = 3072 + 256 = 3328, K=1024)
    hmma_gemm_kernel<<<dim3(T_LEN / 128, (3 * HID + 2 * OUTD) / 128, BATCH), 256, SMEM>>>(
        w2r1, bT, sptr, srptr, 3 * HID, 2 * OUTD, HID);

    lif_fold_kernel<<<N_CHAINS / 256, 256>>>(v1, s1, 1);   // also writes s1^T f16 to bT
    fold_readout_kernel<<<(BATCH * OUTD * T_LEN / 4) / 256, 256>>>(r0);

    // readout 2 (M=256, K=1024)
    hmma_gemm_kernel<<<dim3(T_LEN / 128, 2 * OUTD / 128, BATCH), 256, SMEM>>>(
        r2h, bT, sptr, srptr, 0, 2 * OUTD, HID);
    fold_readout_kernel<<<(BATCH * OUTD * T_LEN / 4) / 256, 256>>>(r1);

    finalize_counts_kernel<<<1, 1>>>(out + CNTOFF);
}